// round 12
// baseline (speedup 1.0000x reference)
#include <cuda_runtime.h>
#include <cuda_bf16.h>
#include <cstdint>
#include <math.h>

#define BS 2
#define CH 128
#define NS 16384
#define MM 4096
#define C1 16
#define C2 64
#define NCHUNK 32
#define MSPLIT 4
#define LOG2E 1.4426950408889634f

// conflict-free strides for 64-bit LDS (words)
#define STH_STRIDE 24
#define SPH_STRIDE 24
#define SGH_STRIDE 40

// Pair-interleave: within each 8-word group, word t -> pos (t<4 ? 2t : 2(t-4)+1)
// so consumer pairs (t, t+4) are adjacent (one LDS.64 / LDG.64).
__host__ __device__ __forceinline__ int pperm(int t){ return (t < 4) ? 2*t : 2*(t-4)+1; }

// ---------------- scratch (device globals; no allocs allowed) ----------------
__device__ __align__(16) float    d_phifull[BS*NS*C1];  // tanh(phi) fp32, pre-pool
__device__ __align__(16) float    d_gfull  [BS*NS*C2];  // g proj fp32, pre-pool
__device__ __align__(16) uint32_t d_thB    [BS*NS*16];  // theta rows: [8 hi][8 lo], pair-interleaved
__device__ __align__(16) uint32_t d_phB    [BS*MM*16];  // pooled phi rows, same layout
__device__ __align__(16) uint32_t d_gthi   [BS*64*64*32]; // ghat tiles, pair-interleaved m-words
__device__ float d_denomp[BS*MM*NCHUNK];
__device__ float d_rdenom[BS*MM];
__device__ __align__(16) float d_attng[MSPLIT*BS*NS*C2]; // m-split partial buffers

// ---------------- helpers ----------------
__device__ __forceinline__ float ex2f(float x){ float r; asm("ex2.approx.f32 %0, %1;" : "=f"(r) : "f"(x)); return r; }
__device__ __forceinline__ uint32_t cvt_bf16x2(float lo, float hi){
    uint32_t r; asm("cvt.rn.bf16x2.f32 %0, %1, %2;" : "=r"(r) : "f"(hi), "f"(lo)); return r;
}
__device__ __forceinline__ void split2(float v0, float v1, uint32_t& whi, uint32_t& wlo){
    whi = cvt_bf16x2(v0, v1);
    float r0 = v0 - __uint_as_float(whi << 16);
    float r1 = v1 - __uint_as_float(whi & 0xFFFF0000u);
    wlo = cvt_bf16x2(r0, r1);
}
__device__ __forceinline__ void mma_bf16(float* d, const uint32_t* a, uint32_t b0, uint32_t b1){
    asm volatile("mma.sync.aligned.m16n8k16.row.col.f32.bf16.bf16.f32 "
        "{%0,%1,%2,%3}, {%4,%5,%6,%7}, {%8,%9}, {%0,%1,%2,%3};"
        : "+f"(d[0]), "+f"(d[1]), "+f"(d[2]), "+f"(d[3])
        : "r"(a[0]), "r"(a[1]), "r"(a[2]), "r"(a[3]), "r"(b0), "r"(b1));
}
__device__ __forceinline__ void cp16(uint32_t saddr, const void* g){
    asm volatile("cp.async.cg.shared.global [%0], [%1], 16;" :: "r"(saddr), "l"(g));
}
__device__ __forceinline__ void cp_commit(){ asm volatile("cp.async.commit_group;" ::: "memory"); }
__device__ __forceinline__ void cp_wait0(){ asm volatile("cp.async.wait_group 0;" ::: "memory"); }
__device__ __forceinline__ void cp_wait1(){ asm volatile("cp.async.wait_group 1;" ::: "memory"); }

// ---------------- K1a: theta & phi projections ----------------
__global__ void __launch_bounds__(128)
proj16_kernel(const float* __restrict__ x,
              const float* __restrict__ wth, const float* __restrict__ bth,
              const float* __restrict__ wph, const float* __restrict__ bph) {
    __shared__ float swt[CH*C1];
    __shared__ float swp[CH*C1];
    __shared__ float sbt[C1], sbp[C1];
    int tid = threadIdx.x;
    for (int i = tid; i < CH*C1; i += 128) {
        int o = i >> 7, c = i & 127;
        swt[c*C1 + o] = wth[i];
        swp[c*C1 + o] = wph[i];
    }
    if (tid < C1) { sbt[tid] = bth[tid]; sbp[tid] = bph[tid]; }
    __syncthreads();

    int b = blockIdx.y;
    int s = blockIdx.x * 128 + tid;
    const float* xp = x + (size_t)b*CH*NS + s;

    float4 t4[4], p4[4];
#pragma unroll
    for (int j = 0; j < 4; j++) {
        t4[j] = make_float4(sbt[4*j], sbt[4*j+1], sbt[4*j+2], sbt[4*j+3]);
        p4[j] = make_float4(sbp[4*j], sbp[4*j+1], sbp[4*j+2], sbp[4*j+3]);
    }
#pragma unroll 4
    for (int c = 0; c < CH; c++) {
        float xv = xp[(size_t)c*NS];
        const float4* wt4 = (const float4*)(swt + c*C1);
        const float4* wp4 = (const float4*)(swp + c*C1);
#pragma unroll
        for (int j = 0; j < 4; j++) {
            float4 w = wt4[j];
            t4[j].x = fmaf(xv, w.x, t4[j].x); t4[j].y = fmaf(xv, w.y, t4[j].y);
            t4[j].z = fmaf(xv, w.z, t4[j].z); t4[j].w = fmaf(xv, w.w, t4[j].w);
            float4 v = wp4[j];
            p4[j].x = fmaf(xv, v.x, p4[j].x); p4[j].y = fmaf(xv, v.y, p4[j].y);
            p4[j].z = fmaf(xv, v.z, p4[j].z); p4[j].w = fmaf(xv, v.w, p4[j].w);
        }
    }
    size_t row = (size_t)b*NS + s;
    float4* po = (float4*)&d_phifull[row*C1];
#pragma unroll
    for (int j = 0; j < 4; j++)
        po[j] = make_float4(tanhf(p4[j].x), tanhf(p4[j].y), tanhf(p4[j].z), tanhf(p4[j].w));
    float tv[16];
#pragma unroll
    for (int j = 0; j < 4; j++) {
        tv[4*j+0] = tanhf(t4[j].x)*LOG2E; tv[4*j+1] = tanhf(t4[j].y)*LOG2E;
        tv[4*j+2] = tanhf(t4[j].z)*LOG2E; tv[4*j+3] = tanhf(t4[j].w)*LOG2E;
    }
    uint32_t w2[16];
#pragma unroll
    for (int k = 0; k < 8; k++) {
        uint32_t hi, lo;
        split2(tv[2*k], tv[2*k+1], hi, lo);
        w2[pperm(k)] = hi;
        w2[8 + pperm(k)] = lo;
    }
    uint4* dst = (uint4*)&d_thB[row*16];
    dst[0] = make_uint4(w2[0],w2[1],w2[2],w2[3]);
    dst[1] = make_uint4(w2[4],w2[5],w2[6],w2[7]);
    dst[2] = make_uint4(w2[8],w2[9],w2[10],w2[11]);
    dst[3] = make_uint4(w2[12],w2[13],w2[14],w2[15]);
}

// ---------------- K1b: g projection (fp32, pre-pool) ----------------
__global__ void __launch_bounds__(128)
proj64_kernel(const float* __restrict__ x,
              const float* __restrict__ wg, const float* __restrict__ bg) {
    __shared__ float sw[CH*C2];
    __shared__ float sb[C2];
    int tid = threadIdx.x;
    for (int i = tid; i < CH*C2; i += 128) {
        int o = i >> 7, c = i & 127;
        sw[c*C2 + o] = wg[i];
    }
    if (tid < C2) sb[tid] = bg[tid];
    __syncthreads();

    int b = blockIdx.y;
    int s = blockIdx.x * 128 + tid;
    const float* xp = x + (size_t)b*CH*NS + s;

    float4 a[16];
#pragma unroll
    for (int j = 0; j < 16; j++)
        a[j] = make_float4(sb[4*j], sb[4*j+1], sb[4*j+2], sb[4*j+3]);
#pragma unroll 2
    for (int c = 0; c < CH; c++) {
        float xv = xp[(size_t)c*NS];
        const float4* w4 = (const float4*)(sw + c*C2);
#pragma unroll
        for (int j = 0; j < 16; j++) {
            float4 w = w4[j];
            a[j].x = fmaf(xv, w.x, a[j].x); a[j].y = fmaf(xv, w.y, a[j].y);
            a[j].z = fmaf(xv, w.z, a[j].z); a[j].w = fmaf(xv, w.w, a[j].w);
        }
    }
    float4* go = (float4*)&d_gfull[((size_t)b*NS + s)*C2];
#pragma unroll
    for (int j = 0; j < 16; j++) go[j] = a[j];
}

// ---------------- K2a: pool phi -> split hi/lo rows (pair-interleaved) -------
__global__ void pool16_kernel() {
    int idx = blockIdx.x * 128 + threadIdx.x;     // BS*MM
    if (idx >= BS*MM) return;
    int b = idx >> 12, m = idx & (MM-1);
    int n = m >> 8, wp = (m >> 4) & 15, hp = m & 15;
    int sbase = n*1024 + wp*64 + hp*2;
    const float4* src = (const float4*)d_phifull + ((size_t)b*NS)*4;
    float v[16];
#pragma unroll
    for (int q = 0; q < 4; q++) {
        float4 v0 = src[(size_t)(sbase     )*4 + q];
        float4 v1 = src[(size_t)(sbase + 1 )*4 + q];
        float4 v2 = src[(size_t)(sbase + 32)*4 + q];
        float4 v3 = src[(size_t)(sbase + 33)*4 + q];
        v[4*q+0] = fmaxf(fmaxf(v0.x, v1.x), fmaxf(v2.x, v3.x));
        v[4*q+1] = fmaxf(fmaxf(v0.y, v1.y), fmaxf(v2.y, v3.y));
        v[4*q+2] = fmaxf(fmaxf(v0.z, v1.z), fmaxf(v2.z, v3.z));
        v[4*q+3] = fmaxf(fmaxf(v0.w, v1.w), fmaxf(v2.w, v3.w));
    }
    uint32_t w2[16];
#pragma unroll
    for (int k = 0; k < 8; k++) {
        uint32_t hi, lo;
        split2(v[2*k], v[2*k+1], hi, lo);
        w2[pperm(k)] = hi;
        w2[8 + pperm(k)] = lo;
    }
    uint4* dst = (uint4*)&d_phB[(size_t)idx*16];
    dst[0] = make_uint4(w2[0],w2[1],w2[2],w2[3]);
    dst[1] = make_uint4(w2[4],w2[5],w2[6],w2[7]);
    dst[2] = make_uint4(w2[8],w2[9],w2[10],w2[11]);
    dst[3] = make_uint4(w2[12],w2[13],w2[14],w2[15]);
}

// ---------------- K3: denominators via warp MMA (S' = phi . theta^T) ----------
__global__ void __launch_bounds__(128)
denom_mma_kernel() {
    __shared__ __align__(16) uint32_t sth[2][128*STH_STRIDE];   // 2 x 12 KB, conflict-free LDS.64
    int tid = threadIdx.x, wid = tid >> 5, lane = tid & 31;
    int gid = lane >> 2, tig = lane & 3;
    int b = blockIdx.z, mt = blockIdx.x, chunk = blockIdx.y;

    int m0 = mt*128 + wid*32;
    uint32_t pa_h[2][4], pa_l[2][4];
#pragma unroll
    for (int sub = 0; sub < 2; sub++) {
        const uint32_t* ph = d_phB + (size_t)(b*MM + m0 + sub*16)*16;
        uint2 h0 = *(const uint2*)&ph[gid*16     + 2*tig];
        uint2 h1 = *(const uint2*)&ph[(gid+8)*16 + 2*tig];
        uint2 l0 = *(const uint2*)&ph[gid*16     + 8 + 2*tig];
        uint2 l1 = *(const uint2*)&ph[(gid+8)*16 + 8 + 2*tig];
        pa_h[sub][0] = h0.x; pa_h[sub][1] = h1.x; pa_h[sub][2] = h0.y; pa_h[sub][3] = h1.y;
        pa_l[sub][0] = l0.x; pa_l[sub][1] = l1.x; pa_l[sub][2] = l0.y; pa_l[sub][3] = l1.y;
    }

    int nbase = chunk*(NS/NCHUNK);
    auto load_tile = [&](int st, int buf){
        const uint4* src = (const uint4*)(d_thB + (size_t)(b*NS + nbase + st*128 + tid)*16);
        uint32_t dst = (uint32_t)__cvta_generic_to_shared(&sth[buf][tid*STH_STRIDE]);
#pragma unroll
        for (int q = 0; q < 4; q++) cp16(dst + q*16, src + q);
    };

    float acc[2][2] = {{0.f,0.f},{0.f,0.f}};
    load_tile(0, 0); cp_commit();
    const int NT = (NS/NCHUNK)/128;   // 4
    for (int st = 0; st < NT; st++) {
        int cur = st & 1;
        if (st + 1 < NT) { load_tile(st+1, cur^1); cp_commit(); cp_wait1(); }
        else cp_wait0();
        __syncthreads();
#pragma unroll 4
        for (int s8 = 0; s8 < 16; s8++) {
            int r = (s8*8 + gid)*STH_STRIDE;
            uint2 bh = *(const uint2*)&sth[cur][r + 2*tig];
            uint2 bl = *(const uint2*)&sth[cur][r + 8 + 2*tig];
            float d0[4] = {0.f,0.f,0.f,0.f};
            float d1[4] = {0.f,0.f,0.f,0.f};
            mma_bf16(d0, pa_h[0], bh.x, bh.y);
            mma_bf16(d1, pa_h[1], bh.x, bh.y);
            mma_bf16(d0, pa_h[0], bl.x, bl.y);
            mma_bf16(d1, pa_h[1], bl.x, bl.y);
            mma_bf16(d0, pa_l[0], bh.x, bh.y);
            mma_bf16(d1, pa_l[1], bh.x, bh.y);
            acc[0][0] += ex2f(d0[0]) + ex2f(d0[1]);
            acc[0][1] += ex2f(d0[2]) + ex2f(d0[3]);
            acc[1][0] += ex2f(d1[0]) + ex2f(d1[1]);
            acc[1][1] += ex2f(d1[2]) + ex2f(d1[3]);
        }
        __syncthreads();
    }
#pragma unroll
    for (int sub = 0; sub < 2; sub++) {
        float a0 = acc[sub][0], a1 = acc[sub][1];
        a0 += __shfl_xor_sync(~0u, a0, 1); a0 += __shfl_xor_sync(~0u, a0, 2);
        a1 += __shfl_xor_sync(~0u, a1, 1); a1 += __shfl_xor_sync(~0u, a1, 2);
        if (tig == 0) {
            d_denomp[(size_t)(b*MM + m0 + sub*16 + gid)*NCHUNK + chunk]     = a0;
            d_denomp[(size_t)(b*MM + m0 + sub*16 + gid + 8)*NCHUNK + chunk] = a1;
        }
    }
}

// ---------------- K4: reciprocal denominators ----------------
__global__ void rdenom_kernel() {
    int i = blockIdx.x * 256 + threadIdx.x;
    if (i >= BS*MM) return;
    const float* p = &d_denomp[(size_t)i*NCHUNK];
    float s = 0.f;
#pragma unroll
    for (int j = 0; j < NCHUNK; j++) s += p[j];
    d_rdenom[i] = 1.0f / s;
}

// ---------------- K5: pool g, fold rdenom, bf16 hi, pair-interleaved ---------
__global__ void pool64_kernel() {
    int idx = blockIdx.x * 256 + threadIdx.x;    // BS*MM*C2
    if (idx >= BS*MM*C2) return;
    int mloc = idx & 63;
    int c    = (idx >> 6) & 63;
    int mt   = (idx >> 12) & 63;
    int b    = idx >> 18;
    int m = mt*64 + mloc;
    int n = m >> 8, wp = (m >> 4) & 15, hp = m & 15;
    int sbase = n*1024 + wp*64 + hp*2;
    const float* g = d_gfull + ((size_t)b*NS)*C2 + c;
    float v = fmaxf(fmaxf(g[(size_t)(sbase)*C2],    g[(size_t)(sbase+1)*C2]),
                    fmaxf(g[(size_t)(sbase+32)*C2], g[(size_t)(sbase+33)*C2]));
    v *= d_rdenom[b*MM + m];
    // pair-interleave within each 16-m chunk (8 words)
    int chunk = mloc >> 4, m16 = mloc & 15, w = m16 >> 1, ln = m16 & 1;
    int newmloc = chunk*16 + pperm(w)*2 + ln;
    size_t ei = (size_t)((b*64 + mt)*64 + c)*64 + newmloc;
    ((__nv_bfloat16*)d_gthi)[ei] = __float2bfloat16_rn(v);
}

// ---------------- K6: attention via warp MMA; 4-way m-split; E hi-only MMA2 --
__global__ void __launch_bounds__(256, 2)
attn_mma_kernel() {
    __shared__ __align__(16) uint32_t sphi[2][64*SPH_STRIDE];  // 2 x 6 KB
    __shared__ __align__(16) uint32_t sgh[2][64*SGH_STRIDE];   // 2 x 10 KB
    int tid = threadIdx.x, wid = tid >> 5, lane = tid & 31;
    int gid = lane >> 2, tig = lane & 3;
    int b = blockIdx.y, nt = blockIdx.x, z = blockIdx.z;
    int n0 = nt*128 + wid*16;

    // theta A fragments (loop-invariant), 16 rows per warp
    const uint32_t* th = d_thB + (size_t)(b*NS + n0)*16;
    uint32_t tah[4], tal[4];
    {
        uint2 h0 = *(const uint2*)&th[gid*16     + 2*tig];
        uint2 h1 = *(const uint2*)&th[(gid+8)*16 + 2*tig];
        uint2 l0 = *(const uint2*)&th[gid*16     + 8 + 2*tig];
        uint2 l1 = *(const uint2*)&th[(gid+8)*16 + 8 + 2*tig];
        tah[0] = h0.x; tah[1] = h1.x; tah[2] = h0.y; tah[3] = h1.y;
        tal[0] = l0.x; tal[1] = l1.x; tal[2] = l0.y; tal[3] = l1.y;
    }

    auto load_tile = [&](int mt, int buf){
        int row = tid >> 2, q = tid & 3;
        uint32_t pd = (uint32_t)__cvta_generic_to_shared(&sphi[buf][row*SPH_STRIDE + q*4]);
        cp16(pd, d_phB + (size_t)(b*MM + mt*64 + row)*16 + q*4);
        const uint32_t* gsrc = d_gthi + (size_t)((b*64 + mt)*64 + row)*32 + q*8;
        uint32_t gd = (uint32_t)__cvta_generic_to_shared(&sgh[buf][row*SGH_STRIDE + q*8]);
        cp16(gd,      gsrc);
        cp16(gd + 16, gsrc + 4);
    };

    float acc[8][4];
#pragma unroll
    for (int ct = 0; ct < 8; ct++)
#pragma unroll
        for (int j = 0; j < 4; j++) acc[ct][j] = 0.f;

    const int NTILE = 64/MSPLIT;   // 16
    int mt0 = z*NTILE;
    load_tile(mt0, 0); cp_commit();
    for (int t = 0; t < NTILE; t++) {
        int cur = t & 1;
        if (t + 1 < NTILE) { load_tile(mt0 + t + 1, cur^1); cp_commit(); cp_wait1(); }
        else cp_wait0();
        __syncthreads();

#pragma unroll
        for (int k = 0; k < 4; k++) {
            uint32_t aeh[4];
            float u0[4] = {0.f,0.f,0.f,0.f};
            float v0[4] = {0.f,0.f,0.f,0.f};
            float u1[4] = {0.f,0.f,0.f,0.f};
            float v1[4] = {0.f,0.f,0.f,0.f};
            {
                int r = ((2*k)*8 + gid)*SPH_STRIDE;
                uint2 bh = *(const uint2*)&sphi[cur][r + 2*tig];
                uint2 bl = *(const uint2*)&sphi[cur][r + 8 + 2*tig];
                mma_bf16(u0, tah, bh.x, bh.y);      // independent chain 1
                mma_bf16(v0, tal, bh.x, bh.y);      // chain 2 (2-deep)
                mma_bf16(v0, tah, bl.x, bl.y);
            }
            {
                int r = ((2*k+1)*8 + gid)*SPH_STRIDE;
                uint2 bh = *(const uint2*)&sphi[cur][r + 2*tig];
                uint2 bl = *(const uint2*)&sphi[cur][r + 8 + 2*tig];
                mma_bf16(u1, tah, bh.x, bh.y);
                mma_bf16(v1, tal, bh.x, bh.y);
                mma_bf16(v1, tah, bl.x, bl.y);
            }
            aeh[0] = cvt_bf16x2(ex2f(u0[0]+v0[0]), ex2f(u0[1]+v0[1]));
            aeh[1] = cvt_bf16x2(ex2f(u0[2]+v0[2]), ex2f(u0[3]+v0[3]));
            aeh[2] = cvt_bf16x2(ex2f(u1[0]+v1[0]), ex2f(u1[1]+v1[1]));
            aeh[3] = cvt_bf16x2(ex2f(u1[2]+v1[2]), ex2f(u1[3]+v1[3]));
#pragma unroll
            for (int ct = 0; ct < 8; ct++) {
                int cbase = (ct*8 + gid)*SGH_STRIDE + 8*k;
                uint2 bg = *(const uint2*)&sgh[cur][cbase + 2*tig];
                mma_bf16(acc[ct], aeh, bg.x, bg.y);
            }
        }
        __syncthreads();
    }

    // write partial attn_g for this m-split
    float* outb = d_attng + (size_t)z*BS*NS*C2;
    int n = n0 + gid;
#pragma unroll
    for (int ct = 0; ct < 8; ct++) {
        int c = ct*8 + tig*2;
        *(float2*)&outb[(size_t)(b*NS + n)*C2 + c]     = make_float2(acc[ct][0], acc[ct][1]);
        *(float2*)&outb[(size_t)(b*NS + n + 8)*C2 + c] = make_float2(acc[ct][2], acc[ct][3]);
    }
}

// ---------------- K7: final 64->128 conv + residual blend --------------------
__global__ void __launch_bounds__(128)
out_kernel(const float* __restrict__ x,
           const float* __restrict__ wag, const float* __restrict__ bag,
           const float* __restrict__ gamma, float* __restrict__ out) {
    __shared__ float sw[CH*C2];
    __shared__ float sb[CH];
    int tid = threadIdx.x;
    for (int i = tid; i < CH*C2; i += 128) sw[i] = wag[i];
    sb[tid] = bag[tid];
    __syncthreads();

    float alpha = 1.0f / (1.0f + expf(-gamma[0]));
    int b = blockIdx.y;
    int s = blockIdx.x * 128 + tid;

    float4 a[16];
    {
        const float4* ap0 = (const float4*)&d_attng[((size_t)b*NS + s)*C2];
        const float4* ap1 = (const float4*)&d_attng[(size_t)1*BS*NS*C2 + ((size_t)b*NS + s)*C2];
        const float4* ap2 = (const float4*)&d_attng[(size_t)2*BS*NS*C2 + ((size_t)b*NS + s)*C2];
        const float4* ap3 = (const float4*)&d_attng[(size_t)3*BS*NS*C2 + ((size_t)b*NS + s)*C2];
#pragma unroll
        for (int j = 0; j < 16; j++) {
            float4 u = ap0[j], v = ap1[j], w = ap2[j], q = ap3[j];
            a[j] = make_float4((u.x + v.x) + (w.x + q.x), (u.y + v.y) + (w.y + q.y),
                               (u.z + v.z) + (w.z + q.z), (u.w + v.w) + (w.w + q.w));
        }
    }

    const float* xp = x + (size_t)b*CH*NS + s;
    float* o0 = out + (size_t)b*CH*NS + s;
    float* o1 = o0 + (size_t)BS*CH*NS;

#pragma unroll 2
    for (int o = 0; o < CH; o++) {
        const float4* wr = (const float4*)(sw + o*C2);
        float y0 = sb[o], y1 = 0.f, y2 = 0.f, y3 = 0.f;
#pragma unroll
        for (int j = 0; j < 16; j += 4) {
            float4 w;
            w = wr[j+0]; y0 = fmaf(a[j+0].x, w.x, y0); y0 = fmaf(a[j+0].y, w.y, y0);
                         y0 = fmaf(a[j+0].z, w.z, y0); y0 = fmaf(a[j+0].w, w.w, y0);
            w = wr[j+1]; y1 = fmaf(a[j+1].x, w.x, y1); y1 = fmaf(a[j+1].y, w.y, y1);
                         y1 = fmaf(a[j+1].z, w.z, y1); y1 = fmaf(a[j+1].w, w.w, y1);
            w = wr[j+2]; y2 = fmaf(a[j+2].x, w.x, y2); y2 = fmaf(a[j+2].y, w.y, y2);
                         y2 = fmaf(a[j+2].z, w.z, y2); y2 = fmaf(a[j+2].w, w.w, y2);
            w = wr[j+3]; y3 = fmaf(a[j+3].x, w.x, y3); y3 = fmaf(a[j+3].y, w.y, y3);
                         y3 = fmaf(a[j+3].z, w.z, y3); y3 = fmaf(a[j+3].w, w.w, y3);
        }
        float y = (y0 + y1) + (y2 + y3);
        float xv = xp[(size_t)o*NS];
        o0[(size_t)o*NS] = (1.0f - alpha)*xv + alpha*y;
        o1[(size_t)o*NS] = y;
    }
}

// ---------------- launch ----------------
extern "C" void kernel_launch(void* const* d_in, const int* in_sizes, int n_in,
                              void* d_out, int out_size) {
    const float* x     = (const float*)d_in[0];
    const float* wth   = (const float*)d_in[1];
    const float* bth   = (const float*)d_in[2];
    const float* wph   = (const float*)d_in[3];
    const float* bph   = (const float*)d_in[4];
    const float* wg    = (const float*)d_in[5];
    const float* bg    = (const float*)d_in[6];
    const float* wag   = (const float*)d_in[7];
    const float* bag   = (const float*)d_in[8];
    const float* gamma = (const float*)d_in[9];
    float* out = (float*)d_out;

    proj16_kernel<<<dim3(NS/128, BS), 128>>>(x, wth, bth, wph, bph);
    proj64_kernel<<<dim3(NS/128, BS), 128>>>(x, wg, bg);
    pool16_kernel<<<(BS*MM + 127)/128, 128>>>();
    denom_mma_kernel<<<dim3(MM/128, NCHUNK, BS), 128>>>();
    rdenom_kernel<<<(BS*MM + 255)/256, 256>>>();
    pool64_kernel<<<(BS*MM*C2 + 255)/256, 256>>>();
    attn_mma_kernel<<<dim3(NS/128, BS, MSPLIT), 256>>>();
    out_kernel<<<dim3(NS/128, BS), 128>>>(x, wag, bag, gamma, out);
}

// round 13
// speedup vs baseline: 1.0375x; 1.0375x over previous
#include <cuda_runtime.h>
#include <cuda_bf16.h>
#include <cstdint>
#include <math.h>

#define BS 2
#define CH 128
#define NS 16384
#define MM 4096
#define C1 16
#define C2 64
#define NCHUNK 32
#define LOG2E 1.4426950408889634f

// conflict-free strides for 64-bit LDS (words)
#define STH_STRIDE 24
#define SPH_STRIDE 24
#define SGH_STRIDE 40

// Pair-interleave: within each 8-word group, word t -> pos (t<4 ? 2t : 2(t-4)+1)
// so consumer pairs (t, t+4) are adjacent (one LDS.64 / LDG.64).
__host__ __device__ __forceinline__ int pperm(int t){ return (t < 4) ? 2*t : 2*(t-4)+1; }

// ---------------- scratch (device globals; no allocs allowed) ----------------
__device__ __align__(16) float    d_phifull[BS*NS*C1];  // tanh(phi) fp32, pre-pool
__device__ __align__(16) float    d_gfull  [BS*NS*C2];  // g proj fp32, pre-pool
__device__ __align__(16) uint32_t d_thB    [BS*NS*16];  // theta rows: [8 hi][8 lo], pair-interleaved
__device__ __align__(16) uint32_t d_phB    [BS*MM*16];  // pooled phi rows, same layout
__device__ __align__(16) uint32_t d_gthi   [BS*64*64*32]; // ghat tiles, pair-interleaved m-words
__device__ float d_denomp[BS*MM*NCHUNK];
__device__ float d_rdenom[BS*MM];
__device__ __align__(16) float d_attng[2*BS*NS*C2];     // two m-split partial buffers

// ---------------- helpers ----------------
__device__ __forceinline__ float ex2f(float x){ float r; asm("ex2.approx.f32 %0, %1;" : "=f"(r) : "f"(x)); return r; }
__device__ __forceinline__ uint32_t cvt_bf16x2(float lo, float hi){
    uint32_t r; asm("cvt.rn.bf16x2.f32 %0, %1, %2;" : "=r"(r) : "f"(hi), "f"(lo)); return r;
}
__device__ __forceinline__ void split2(float v0, float v1, uint32_t& whi, uint32_t& wlo){
    whi = cvt_bf16x2(v0, v1);
    float r0 = v0 - __uint_as_float(whi << 16);
    float r1 = v1 - __uint_as_float(whi & 0xFFFF0000u);
    wlo = cvt_bf16x2(r0, r1);
}
__device__ __forceinline__ void mma_bf16(float* d, const uint32_t* a, uint32_t b0, uint32_t b1){
    asm volatile("mma.sync.aligned.m16n8k16.row.col.f32.bf16.bf16.f32 "
        "{%0,%1,%2,%3}, {%4,%5,%6,%7}, {%8,%9}, {%0,%1,%2,%3};"
        : "+f"(d[0]), "+f"(d[1]), "+f"(d[2]), "+f"(d[3])
        : "r"(a[0]), "r"(a[1]), "r"(a[2]), "r"(a[3]), "r"(b0), "r"(b1));
}
__device__ __forceinline__ void cp16(uint32_t saddr, const void* g){
    asm volatile("cp.async.cg.shared.global [%0], [%1], 16;" :: "r"(saddr), "l"(g));
}
__device__ __forceinline__ void cp_commit(){ asm volatile("cp.async.commit_group;" ::: "memory"); }
__device__ __forceinline__ void cp_wait0(){ asm volatile("cp.async.wait_group 0;" ::: "memory"); }
__device__ __forceinline__ void cp_wait1(){ asm volatile("cp.async.wait_group 1;" ::: "memory"); }

// ---------------- K1a: theta & phi projections ----------------
__global__ void __launch_bounds__(128)
proj16_kernel(const float* __restrict__ x,
              const float* __restrict__ wth, const float* __restrict__ bth,
              const float* __restrict__ wph, const float* __restrict__ bph) {
    __shared__ float swt[CH*C1];
    __shared__ float swp[CH*C1];
    __shared__ float sbt[C1], sbp[C1];
    int tid = threadIdx.x;
    for (int i = tid; i < CH*C1; i += 128) {
        int o = i >> 7, c = i & 127;
        swt[c*C1 + o] = wth[i];
        swp[c*C1 + o] = wph[i];
    }
    if (tid < C1) { sbt[tid] = bth[tid]; sbp[tid] = bph[tid]; }
    __syncthreads();

    int b = blockIdx.y;
    int s = blockIdx.x * 128 + tid;
    const float* xp = x + (size_t)b*CH*NS + s;

    float4 t4[4], p4[4];
#pragma unroll
    for (int j = 0; j < 4; j++) {
        t4[j] = make_float4(sbt[4*j], sbt[4*j+1], sbt[4*j+2], sbt[4*j+3]);
        p4[j] = make_float4(sbp[4*j], sbp[4*j+1], sbp[4*j+2], sbp[4*j+3]);
    }
#pragma unroll 4
    for (int c = 0; c < CH; c++) {
        float xv = xp[(size_t)c*NS];
        const float4* wt4 = (const float4*)(swt + c*C1);
        const float4* wp4 = (const float4*)(swp + c*C1);
#pragma unroll
        for (int j = 0; j < 4; j++) {
            float4 w = wt4[j];
            t4[j].x = fmaf(xv, w.x, t4[j].x); t4[j].y = fmaf(xv, w.y, t4[j].y);
            t4[j].z = fmaf(xv, w.z, t4[j].z); t4[j].w = fmaf(xv, w.w, t4[j].w);
            float4 v = wp4[j];
            p4[j].x = fmaf(xv, v.x, p4[j].x); p4[j].y = fmaf(xv, v.y, p4[j].y);
            p4[j].z = fmaf(xv, v.z, p4[j].z); p4[j].w = fmaf(xv, v.w, p4[j].w);
        }
    }
    size_t row = (size_t)b*NS + s;
    float4* po = (float4*)&d_phifull[row*C1];
#pragma unroll
    for (int j = 0; j < 4; j++)
        po[j] = make_float4(tanhf(p4[j].x), tanhf(p4[j].y), tanhf(p4[j].z), tanhf(p4[j].w));
    float tv[16];
#pragma unroll
    for (int j = 0; j < 4; j++) {
        tv[4*j+0] = tanhf(t4[j].x)*LOG2E; tv[4*j+1] = tanhf(t4[j].y)*LOG2E;
        tv[4*j+2] = tanhf(t4[j].z)*LOG2E; tv[4*j+3] = tanhf(t4[j].w)*LOG2E;
    }
    uint32_t w2[16];
#pragma unroll
    for (int k = 0; k < 8; k++) {
        uint32_t hi, lo;
        split2(tv[2*k], tv[2*k+1], hi, lo);
        w2[pperm(k)] = hi;
        w2[8 + pperm(k)] = lo;
    }
    uint4* dst = (uint4*)&d_thB[row*16];
    dst[0] = make_uint4(w2[0],w2[1],w2[2],w2[3]);
    dst[1] = make_uint4(w2[4],w2[5],w2[6],w2[7]);
    dst[2] = make_uint4(w2[8],w2[9],w2[10],w2[11]);
    dst[3] = make_uint4(w2[12],w2[13],w2[14],w2[15]);
}

// ---------------- K1b: g projection (fp32, pre-pool) ----------------
__global__ void __launch_bounds__(128)
proj64_kernel(const float* __restrict__ x,
              const float* __restrict__ wg, const float* __restrict__ bg) {
    __shared__ float sw[CH*C2];
    __shared__ float sb[C2];
    int tid = threadIdx.x;
    for (int i = tid; i < CH*C2; i += 128) {
        int o = i >> 7, c = i & 127;
        sw[c*C2 + o] = wg[i];
    }
    if (tid < C2) sb[tid] = bg[tid];
    __syncthreads();

    int b = blockIdx.y;
    int s = blockIdx.x * 128 + tid;
    const float* xp = x + (size_t)b*CH*NS + s;

    float4 a[16];
#pragma unroll
    for (int j = 0; j < 16; j++)
        a[j] = make_float4(sb[4*j], sb[4*j+1], sb[4*j+2], sb[4*j+3]);
#pragma unroll 2
    for (int c = 0; c < CH; c++) {
        float xv = xp[(size_t)c*NS];
        const float4* w4 = (const float4*)(sw + c*C2);
#pragma unroll
        for (int j = 0; j < 16; j++) {
            float4 w = w4[j];
            a[j].x = fmaf(xv, w.x, a[j].x); a[j].y = fmaf(xv, w.y, a[j].y);
            a[j].z = fmaf(xv, w.z, a[j].z); a[j].w = fmaf(xv, w.w, a[j].w);
        }
    }
    float4* go = (float4*)&d_gfull[((size_t)b*NS + s)*C2];
#pragma unroll
    for (int j = 0; j < 16; j++) go[j] = a[j];
}

// ---------------- K2a: pool phi -> split hi/lo rows (pair-interleaved) -------
__global__ void pool16_kernel() {
    int idx = blockIdx.x * 128 + threadIdx.x;     // BS*MM
    if (idx >= BS*MM) return;
    int b = idx >> 12, m = idx & (MM-1);
    int n = m >> 8, wp = (m >> 4) & 15, hp = m & 15;
    int sbase = n*1024 + wp*64 + hp*2;
    const float4* src = (const float4*)d_phifull + ((size_t)b*NS)*4;
    float v[16];
#pragma unroll
    for (int q = 0; q < 4; q++) {
        float4 v0 = src[(size_t)(sbase     )*4 + q];
        float4 v1 = src[(size_t)(sbase + 1 )*4 + q];
        float4 v2 = src[(size_t)(sbase + 32)*4 + q];
        float4 v3 = src[(size_t)(sbase + 33)*4 + q];
        v[4*q+0] = fmaxf(fmaxf(v0.x, v1.x), fmaxf(v2.x, v3.x));
        v[4*q+1] = fmaxf(fmaxf(v0.y, v1.y), fmaxf(v2.y, v3.y));
        v[4*q+2] = fmaxf(fmaxf(v0.z, v1.z), fmaxf(v2.z, v3.z));
        v[4*q+3] = fmaxf(fmaxf(v0.w, v1.w), fmaxf(v2.w, v3.w));
    }
    uint32_t w2[16];
#pragma unroll
    for (int k = 0; k < 8; k++) {
        uint32_t hi, lo;
        split2(v[2*k], v[2*k+1], hi, lo);
        w2[pperm(k)] = hi;
        w2[8 + pperm(k)] = lo;
    }
    uint4* dst = (uint4*)&d_phB[(size_t)idx*16];
    dst[0] = make_uint4(w2[0],w2[1],w2[2],w2[3]);
    dst[1] = make_uint4(w2[4],w2[5],w2[6],w2[7]);
    dst[2] = make_uint4(w2[8],w2[9],w2[10],w2[11]);
    dst[3] = make_uint4(w2[12],w2[13],w2[14],w2[15]);
}

// ---------------- K3: denominators via warp MMA (S' = phi . theta^T) ----------
__global__ void __launch_bounds__(128)
denom_mma_kernel() {
    __shared__ __align__(16) uint32_t sth[2][128*STH_STRIDE];   // 2 x 12 KB, conflict-free LDS.64
    int tid = threadIdx.x, wid = tid >> 5, lane = tid & 31;
    int gid = lane >> 2, tig = lane & 3;
    int b = blockIdx.z, mt = blockIdx.x, chunk = blockIdx.y;

    int m0 = mt*128 + wid*32;
    uint32_t pa_h[2][4], pa_l[2][4];
#pragma unroll
    for (int sub = 0; sub < 2; sub++) {
        const uint32_t* ph = d_phB + (size_t)(b*MM + m0 + sub*16)*16;
        uint2 h0 = *(const uint2*)&ph[gid*16     + 2*tig];
        uint2 h1 = *(const uint2*)&ph[(gid+8)*16 + 2*tig];
        uint2 l0 = *(const uint2*)&ph[gid*16     + 8 + 2*tig];
        uint2 l1 = *(const uint2*)&ph[(gid+8)*16 + 8 + 2*tig];
        pa_h[sub][0] = h0.x; pa_h[sub][1] = h1.x; pa_h[sub][2] = h0.y; pa_h[sub][3] = h1.y;
        pa_l[sub][0] = l0.x; pa_l[sub][1] = l1.x; pa_l[sub][2] = l0.y; pa_l[sub][3] = l1.y;
    }

    int nbase = chunk*(NS/NCHUNK);
    auto load_tile = [&](int st, int buf){
        const uint4* src = (const uint4*)(d_thB + (size_t)(b*NS + nbase + st*128 + tid)*16);
        uint32_t dst = (uint32_t)__cvta_generic_to_shared(&sth[buf][tid*STH_STRIDE]);
#pragma unroll
        for (int q = 0; q < 4; q++) cp16(dst + q*16, src + q);
    };

    float acc[2][2] = {{0.f,0.f},{0.f,0.f}};
    load_tile(0, 0); cp_commit();
    const int NT = (NS/NCHUNK)/128;   // 4
    for (int st = 0; st < NT; st++) {
        int cur = st & 1;
        if (st + 1 < NT) { load_tile(st+1, cur^1); cp_commit(); cp_wait1(); }
        else cp_wait0();
        __syncthreads();
#pragma unroll 4
        for (int s8 = 0; s8 < 16; s8++) {
            int r = (s8*8 + gid)*STH_STRIDE;
            uint2 bh = *(const uint2*)&sth[cur][r + 2*tig];
            uint2 bl = *(const uint2*)&sth[cur][r + 8 + 2*tig];
            float d0[4] = {0.f,0.f,0.f,0.f};
            float d1[4] = {0.f,0.f,0.f,0.f};
            mma_bf16(d0, pa_h[0], bh.x, bh.y);
            mma_bf16(d1, pa_h[1], bh.x, bh.y);
            mma_bf16(d0, pa_h[0], bl.x, bl.y);
            mma_bf16(d1, pa_h[1], bl.x, bl.y);
            mma_bf16(d0, pa_l[0], bh.x, bh.y);
            mma_bf16(d1, pa_l[1], bh.x, bh.y);
            acc[0][0] += ex2f(d0[0]) + ex2f(d0[1]);
            acc[0][1] += ex2f(d0[2]) + ex2f(d0[3]);
            acc[1][0] += ex2f(d1[0]) + ex2f(d1[1]);
            acc[1][1] += ex2f(d1[2]) + ex2f(d1[3]);
        }
        __syncthreads();
    }
#pragma unroll
    for (int sub = 0; sub < 2; sub++) {
        float a0 = acc[sub][0], a1 = acc[sub][1];
        a0 += __shfl_xor_sync(~0u, a0, 1); a0 += __shfl_xor_sync(~0u, a0, 2);
        a1 += __shfl_xor_sync(~0u, a1, 1); a1 += __shfl_xor_sync(~0u, a1, 2);
        if (tig == 0) {
            d_denomp[(size_t)(b*MM + m0 + sub*16 + gid)*NCHUNK + chunk]     = a0;
            d_denomp[(size_t)(b*MM + m0 + sub*16 + gid + 8)*NCHUNK + chunk] = a1;
        }
    }
}

// ---------------- K4: reciprocal denominators ----------------
__global__ void rdenom_kernel() {
    int i = blockIdx.x * 256 + threadIdx.x;
    if (i >= BS*MM) return;
    const float* p = &d_denomp[(size_t)i*NCHUNK];
    float s = 0.f;
#pragma unroll
    for (int j = 0; j < NCHUNK; j++) s += p[j];
    d_rdenom[i] = 1.0f / s;
}

// ---------------- K5: pool g, fold rdenom, bf16 hi, pair-interleaved ---------
__global__ void pool64_kernel() {
    int idx = blockIdx.x * 256 + threadIdx.x;    // BS*MM*C2
    if (idx >= BS*MM*C2) return;
    int mloc = idx & 63;
    int c    = (idx >> 6) & 63;
    int mt   = (idx >> 12) & 63;
    int b    = idx >> 18;
    int m = mt*64 + mloc;
    int n = m >> 8, wp = (m >> 4) & 15, hp = m & 15;
    int sbase = n*1024 + wp*64 + hp*2;
    const float* g = d_gfull + ((size_t)b*NS)*C2 + c;
    float v = fmaxf(fmaxf(g[(size_t)(sbase)*C2],    g[(size_t)(sbase+1)*C2]),
                    fmaxf(g[(size_t)(sbase+32)*C2], g[(size_t)(sbase+33)*C2]));
    v *= d_rdenom[b*MM + m];
    // pair-interleave within each 16-m chunk (8 words)
    int chunk = mloc >> 4, m16 = mloc & 15, w = m16 >> 1, ln = m16 & 1;
    int newmloc = chunk*16 + pperm(w)*2 + ln;
    size_t ei = (size_t)((b*64 + mt)*64 + c)*64 + newmloc;
    ((__nv_bfloat16*)d_gthi)[ei] = __float2bfloat16_rn(v);
}

// ---------------- K6: attention via warp MMA; 2-way m-split; E hi-only MMA2 --
// 3-stage cp.async pipeline, ONE __syncthreads per tile.
__global__ void __launch_bounds__(256, 2)
attn_mma_kernel() {
    __shared__ __align__(16) uint32_t sphi[3][64*SPH_STRIDE];  // 3 x 6 KB
    __shared__ __align__(16) uint32_t sgh[3][64*SGH_STRIDE];   // 3 x 10 KB
    int tid = threadIdx.x, wid = tid >> 5, lane = tid & 31;
    int gid = lane >> 2, tig = lane & 3;
    int b = blockIdx.y, nt = blockIdx.x, z = blockIdx.z;
    int n0 = nt*128 + wid*16;

    // theta A fragments (loop-invariant), 16 rows per warp
    const uint32_t* th = d_thB + (size_t)(b*NS + n0)*16;
    uint32_t tah[4], tal[4];
    {
        uint2 h0 = *(const uint2*)&th[gid*16     + 2*tig];
        uint2 h1 = *(const uint2*)&th[(gid+8)*16 + 2*tig];
        uint2 l0 = *(const uint2*)&th[gid*16     + 8 + 2*tig];
        uint2 l1 = *(const uint2*)&th[(gid+8)*16 + 8 + 2*tig];
        tah[0] = h0.x; tah[1] = h1.x; tah[2] = h0.y; tah[3] = h1.y;
        tal[0] = l0.x; tal[1] = l1.x; tal[2] = l0.y; tal[3] = l1.y;
    }

    auto load_tile = [&](int mt, int buf){
        int row = tid >> 2, q = tid & 3;
        uint32_t pd = (uint32_t)__cvta_generic_to_shared(&sphi[buf][row*SPH_STRIDE + q*4]);
        cp16(pd, d_phB + (size_t)(b*MM + mt*64 + row)*16 + q*4);
        const uint32_t* gsrc = d_gthi + (size_t)((b*64 + mt)*64 + row)*32 + q*8;
        uint32_t gd = (uint32_t)__cvta_generic_to_shared(&sgh[buf][row*SGH_STRIDE + q*8]);
        cp16(gd,      gsrc);
        cp16(gd + 16, gsrc + 4);
    };

    float acc[8][4];
#pragma unroll
    for (int ct = 0; ct < 8; ct++)
#pragma unroll
        for (int j = 0; j < 4; j++) acc[ct][j] = 0.f;

    const int NTILE = 32;
    int mt0 = z*NTILE;
    load_tile(mt0 + 0, 0); cp_commit();
    load_tile(mt0 + 1, 1); cp_commit();
    for (int t = 0; t < NTILE; t++) {
        int cur = t % 3;
        // groups issued so far: up to tile t+1. Leave newest pending -> tile t done.
        if (t + 1 < NTILE) cp_wait1(); else cp_wait0();
        __syncthreads();   // data of tile t visible to all; all threads done with tile t-1
        if (t + 2 < NTILE) { load_tile(mt0 + t + 2, (t + 2) % 3); cp_commit(); }

#pragma unroll
        for (int k = 0; k < 4; k++) {
            uint32_t aeh[4];
            float s0[4] = {0.f,0.f,0.f,0.f};
            float s1[4] = {0.f,0.f,0.f,0.f};
            {
                int r = ((2*k)*8 + gid)*SPH_STRIDE;
                uint2 bh = *(const uint2*)&sphi[cur][r + 2*tig];
                uint2 bl = *(const uint2*)&sphi[cur][r + 8 + 2*tig];
                mma_bf16(s0, tah, bh.x, bh.y);
                mma_bf16(s0, tal, bh.x, bh.y);
                mma_bf16(s0, tah, bl.x, bl.y);
            }
            {
                int r = ((2*k+1)*8 + gid)*SPH_STRIDE;
                uint2 bh = *(const uint2*)&sphi[cur][r + 2*tig];
                uint2 bl = *(const uint2*)&sphi[cur][r + 8 + 2*tig];
                mma_bf16(s1, tah, bh.x, bh.y);
                mma_bf16(s1, tal, bh.x, bh.y);
                mma_bf16(s1, tah, bl.x, bl.y);
            }
            aeh[0] = cvt_bf16x2(ex2f(s0[0]), ex2f(s0[1]));
            aeh[1] = cvt_bf16x2(ex2f(s0[2]), ex2f(s0[3]));
            aeh[2] = cvt_bf16x2(ex2f(s1[0]), ex2f(s1[1]));
            aeh[3] = cvt_bf16x2(ex2f(s1[2]), ex2f(s1[3]));
#pragma unroll
            for (int ct = 0; ct < 8; ct++) {
                int cbase = (ct*8 + gid)*SGH_STRIDE + 8*k;
                uint2 bg = *(const uint2*)&sgh[cur][cbase + 2*tig];
                mma_bf16(acc[ct], aeh, bg.x, bg.y);
            }
        }
    }

    // write partial attn_g for this m-split
    float* outb = d_attng + (size_t)z*BS*NS*C2;
    int n = n0 + gid;
#pragma unroll
    for (int ct = 0; ct < 8; ct++) {
        int c = ct*8 + tig*2;
        *(float2*)&outb[(size_t)(b*NS + n)*C2 + c]     = make_float2(acc[ct][0], acc[ct][1]);
        *(float2*)&outb[(size_t)(b*NS + n + 8)*C2 + c] = make_float2(acc[ct][2], acc[ct][3]);
    }
}

// ---------------- K7: final 64->128 conv + residual blend --------------------
__global__ void __launch_bounds__(128)
out_kernel(const float* __restrict__ x,
           const float* __restrict__ wag, const float* __restrict__ bag,
           const float* __restrict__ gamma, float* __restrict__ out) {
    __shared__ float sw[CH*C2];
    __shared__ float sb[CH];
    int tid = threadIdx.x;
    for (int i = tid; i < CH*C2; i += 128) sw[i] = wag[i];
    sb[tid] = bag[tid];
    __syncthreads();

    float alpha = 1.0f / (1.0f + expf(-gamma[0]));
    int b = blockIdx.y;
    int s = blockIdx.x * 128 + tid;

    float4 a[16];
    {
        const float4* ap0 = (const float4*)&d_attng[((size_t)b*NS + s)*C2];
        const float4* ap1 = (const float4*)&d_attng[(size_t)BS*NS*C2 + ((size_t)b*NS + s)*C2];
#pragma unroll
        for (int j = 0; j < 16; j++) {
            float4 u = ap0[j], v = ap1[j];
            a[j] = make_float4(u.x + v.x, u.y + v.y, u.z + v.z, u.w + v.w);
        }
    }

    const float* xp = x + (size_t)b*CH*NS + s;
    float* o0 = out + (size_t)b*CH*NS + s;
    float* o1 = o0 + (size_t)BS*CH*NS;

#pragma unroll 2
    for (int o = 0; o < CH; o++) {
        const float4* wr = (const float4*)(sw + o*C2);
        float y0 = sb[o], y1 = 0.f, y2 = 0.f, y3 = 0.f;
#pragma unroll
        for (int j = 0; j < 16; j += 4) {
            float4 w;
            w = wr[j+0]; y0 = fmaf(a[j+0].x, w.x, y0); y0 = fmaf(a[j+0].y, w.y, y0);
                         y0 = fmaf(a[j+0].z, w.z, y0); y0 = fmaf(a[j+0].w, w.w, y0);
            w = wr[j+1]; y1 = fmaf(a[j+1].x, w.x, y1); y1 = fmaf(a[j+1].y, w.y, y1);
                         y1 = fmaf(a[j+1].z, w.z, y1); y1 = fmaf(a[j+1].w, w.w, y1);
            w = wr[j+2]; y2 = fmaf(a[j+2].x, w.x, y2); y2 = fmaf(a[j+2].y, w.y, y2);
                         y2 = fmaf(a[j+2].z, w.z, y2); y2 = fmaf(a[j+2].w, w.w, y2);
            w = wr[j+3]; y3 = fmaf(a[j+3].x, w.x, y3); y3 = fmaf(a[j+3].y, w.y, y3);
                         y3 = fmaf(a[j+3].z, w.z, y3); y3 = fmaf(a[j+3].w, w.w, y3);
        }
        float y = (y0 + y1) + (y2 + y3);
        float xv = xp[(size_t)o*NS];
        o0[(size_t)o*NS] = (1.0f - alpha)*xv + alpha*y;
        o1[(size_t)o*NS] = y;
    }
}

// ---------------- launch ----------------
extern "C" void kernel_launch(void* const* d_in, const int* in_sizes, int n_in,
                              void* d_out, int out_size) {
    const float* x     = (const float*)d_in[0];
    const float* wth   = (const float*)d_in[1];
    const float* bth   = (const float*)d_in[2];
    const float* wph   = (const float*)d_in[3];
    const float* bph   = (const float*)d_in[4];
    const float* wg    = (const float*)d_in[5];
    const float* bg    = (const float*)d_in[6];
    const float* wag   = (const float*)d_in[7];
    const float* bag   = (const float*)d_in[8];
    const float* gamma = (const float*)d_in[9];
    float* out = (float*)d_out;

    proj16_kernel<<<dim3(NS/128, BS), 128>>>(x, wth, bth, wph, bph);
    proj64_kernel<<<dim3(NS/128, BS), 128>>>(x, wg, bg);
    pool16_kernel<<<(BS*MM + 127)/128, 128>>>();
    denom_mma_kernel<<<dim3(MM/128, NCHUNK, BS), 128>>>();
    rdenom_kernel<<<(BS*MM + 255)/256, 256>>>();
    pool64_kernel<<<(BS*MM*C2 + 255)/256, 256>>>();
    attn_mma_kernel<<<dim3(NS/128, BS, 2), 256>>>();
    out_kernel<<<dim3(NS/128, BS), 128>>>(x, wag, bag, gamma, out);
}

// round 15
// speedup vs baseline: 1.1218x; 1.0813x over previous
#include <cuda_runtime.h>
#include <cuda_bf16.h>
#include <cstdint>
#include <math.h>

#define BS 2
#define CH 128
#define NS 16384
#define MM 4096
#define C1 16
#define C2 64
#define NCHUNK 32
#define LOG2E 1.4426950408889634f

// conflict-free strides for 64-bit LDS (words)
#define STH_STRIDE 24
#define SPH_STRIDE 24
#define SGH_STRIDE 40

// Pair-interleave: within each 8-word group, word t -> pos (t<4 ? 2t : 2(t-4)+1)
__host__ __device__ __forceinline__ int pperm(int t){ return (t < 4) ? 2*t : 2*(t-4)+1; }

// ---------------- scratch (device globals; no allocs allowed) ----------------
__device__ __align__(16) float    d_phifull[BS*NS*C1];
__device__ __align__(16) float    d_gfull  [BS*NS*C2];
__device__ __align__(16) uint32_t d_thB    [BS*NS*16];
__device__ __align__(16) uint32_t d_phB    [BS*MM*16];
__device__ __align__(16) uint32_t d_gthi   [BS*64*64*32];
__device__ float d_denomp[BS*MM*NCHUNK];
__device__ float d_rdenom[BS*MM];
__device__ __align__(16) float d_attng[2*BS*NS*C2];

// ---------------- helpers ----------------
__device__ __forceinline__ float ex2f(float x){ float r; asm("ex2.approx.f32 %0, %1;" : "=f"(r) : "f"(x)); return r; }
__device__ __forceinline__ uint32_t cvt_bf16x2(float lo, float hi){
    uint32_t r; asm("cvt.rn.bf16x2.f32 %0, %1, %2;" : "=r"(r) : "f"(hi), "f"(lo)); return r;
}
__device__ __forceinline__ void split2(float v0, float v1, uint32_t& whi, uint32_t& wlo){
    whi = cvt_bf16x2(v0, v1);
    float r0 = v0 - __uint_as_float(whi << 16);
    float r1 = v1 - __uint_as_float(whi & 0xFFFF0000u);
    wlo = cvt_bf16x2(r0, r1);
}
__device__ __forceinline__ void mma_bf16(float* d, const uint32_t* a, uint32_t b0, uint32_t b1){
    asm volatile("mma.sync.aligned.m16n8k16.row.col.f32.bf16.bf16.f32 "
        "{%0,%1,%2,%3}, {%4,%5,%6,%7}, {%8,%9}, {%0,%1,%2,%3};"
        : "+f"(d[0]), "+f"(d[1]), "+f"(d[2]), "+f"(d[3])
        : "r"(a[0]), "r"(a[1]), "r"(a[2]), "r"(a[3]), "r"(b0), "r"(b1));
}
__device__ __forceinline__ void cp16(uint32_t saddr, const void* g){
    asm volatile("cp.async.cg.shared.global [%0], [%1], 16;" :: "r"(saddr), "l"(g));
}
__device__ __forceinline__ void cp_commit(){ asm volatile("cp.async.commit_group;" ::: "memory"); }
__device__ __forceinline__ void cp_wait0(){ asm volatile("cp.async.wait_group 0;" ::: "memory"); }
__device__ __forceinline__ void cp_wait1(){ asm volatile("cp.async.wait_group 1;" ::: "memory"); }

// ---------------- K1a: theta & phi projections (256 thr: half=theta, half=phi) ----
__global__ void __launch_bounds__(256)
proj16_kernel(const float* __restrict__ x,
              const float* __restrict__ wth, const float* __restrict__ bth,
              const float* __restrict__ wph, const float* __restrict__ bph) {
    __shared__ float swt[CH*C1];
    __shared__ float swp[CH*C1];
    __shared__ float sbt[C1], sbp[C1];
    int tid = threadIdx.x;
    for (int i = tid; i < CH*C1; i += 256) {
        int o = i >> 7, c = i & 127;
        swt[c*C1 + o] = wth[i];
        swp[c*C1 + o] = wph[i];
    }
    if (tid < C1) sbt[tid] = bth[tid];
    else if (tid < 2*C1) sbp[tid - C1] = bph[tid - C1];
    __syncthreads();

    int half = tid >> 7;            // 0 = theta, 1 = phi
    int lt   = tid & 127;
    int b = blockIdx.y;
    int s = blockIdx.x * 128 + lt;
    const float* xp = x + (size_t)b*CH*NS + s;
    const float* sw = half ? swp : swt;
    const float* sb = half ? sbp : sbt;

    float4 t4[4];
#pragma unroll
    for (int j = 0; j < 4; j++)
        t4[j] = make_float4(sb[4*j], sb[4*j+1], sb[4*j+2], sb[4*j+3]);
#pragma unroll 4
    for (int c = 0; c < CH; c++) {
        float xv = xp[(size_t)c*NS];
        const float4* w4 = (const float4*)(sw + c*C1);
#pragma unroll
        for (int j = 0; j < 4; j++) {
            float4 w = w4[j];
            t4[j].x = fmaf(xv, w.x, t4[j].x); t4[j].y = fmaf(xv, w.y, t4[j].y);
            t4[j].z = fmaf(xv, w.z, t4[j].z); t4[j].w = fmaf(xv, w.w, t4[j].w);
        }
    }
    size_t row = (size_t)b*NS + s;
    if (half) {
        float4* po = (float4*)&d_phifull[row*C1];
#pragma unroll
        for (int j = 0; j < 4; j++)
            po[j] = make_float4(tanhf(t4[j].x), tanhf(t4[j].y), tanhf(t4[j].z), tanhf(t4[j].w));
    } else {
        float tv[16];
#pragma unroll
        for (int j = 0; j < 4; j++) {
            tv[4*j+0] = tanhf(t4[j].x)*LOG2E; tv[4*j+1] = tanhf(t4[j].y)*LOG2E;
            tv[4*j+2] = tanhf(t4[j].z)*LOG2E; tv[4*j+3] = tanhf(t4[j].w)*LOG2E;
        }
        uint32_t w2[16];
#pragma unroll
        for (int k = 0; k < 8; k++) {
            uint32_t hi, lo;
            split2(tv[2*k], tv[2*k+1], hi, lo);
            w2[pperm(k)] = hi;
            w2[8 + pperm(k)] = lo;
        }
        uint4* dst = (uint4*)&d_thB[row*16];
        dst[0] = make_uint4(w2[0],w2[1],w2[2],w2[3]);
        dst[1] = make_uint4(w2[4],w2[5],w2[6],w2[7]);
        dst[2] = make_uint4(w2[8],w2[9],w2[10],w2[11]);
        dst[3] = make_uint4(w2[12],w2[13],w2[14],w2[15]);
    }
}

// ---------------- K1b: g projection (256 thr: halves split o-range) ----------
__global__ void __launch_bounds__(256)
proj64_kernel(const float* __restrict__ x,
              const float* __restrict__ wg, const float* __restrict__ bg) {
    __shared__ float sw[CH*C2];   // [c][o]
    __shared__ float sb[C2];
    int tid = threadIdx.x;
    for (int i = tid; i < CH*C2; i += 256) {
        int o = i >> 7, c = i & 127;
        sw[c*C2 + o] = wg[i];
    }
    if (tid < C2) sb[tid] = bg[tid];
    __syncthreads();

    int half = tid >> 7;          // o in [half*32, half*32+32)
    int lt   = tid & 127;
    int o0   = half * 32;
    int b = blockIdx.y;
    int s = blockIdx.x * 128 + lt;
    const float* xp = x + (size_t)b*CH*NS + s;

    float4 a[8];
#pragma unroll
    for (int j = 0; j < 8; j++)
        a[j] = make_float4(sb[o0+4*j], sb[o0+4*j+1], sb[o0+4*j+2], sb[o0+4*j+3]);
#pragma unroll 2
    for (int c = 0; c < CH; c++) {
        float xv = xp[(size_t)c*NS];
        const float4* w4 = (const float4*)(sw + c*C2 + o0);
#pragma unroll
        for (int j = 0; j < 8; j++) {
            float4 w = w4[j];
            a[j].x = fmaf(xv, w.x, a[j].x); a[j].y = fmaf(xv, w.y, a[j].y);
            a[j].z = fmaf(xv, w.z, a[j].z); a[j].w = fmaf(xv, w.w, a[j].w);
        }
    }
    float4* go = (float4*)&d_gfull[((size_t)b*NS + s)*C2 + o0];
#pragma unroll
    for (int j = 0; j < 8; j++) go[j] = a[j];
}

// ---------------- K2a: pool phi -> split hi/lo rows (pair-interleaved) -------
__global__ void pool16_kernel() {
    int idx = blockIdx.x * 128 + threadIdx.x;     // BS*MM
    if (idx >= BS*MM) return;
    int b = idx >> 12, m = idx & (MM-1);
    int n = m >> 8, wp = (m >> 4) & 15, hp = m & 15;
    int sbase = n*1024 + wp*64 + hp*2;
    const float4* src = (const float4*)d_phifull + ((size_t)b*NS)*4;
    float v[16];
#pragma unroll
    for (int q = 0; q < 4; q++) {
        float4 v0 = src[(size_t)(sbase     )*4 + q];
        float4 v1 = src[(size_t)(sbase + 1 )*4 + q];
        float4 v2 = src[(size_t)(sbase + 32)*4 + q];
        float4 v3 = src[(size_t)(sbase + 33)*4 + q];
        v[4*q+0] = fmaxf(fmaxf(v0.x, v1.x), fmaxf(v2.x, v3.x));
        v[4*q+1] = fmaxf(fmaxf(v0.y, v1.y), fmaxf(v2.y, v3.y));
        v[4*q+2] = fmaxf(fmaxf(v0.z, v1.z), fmaxf(v2.z, v3.z));
        v[4*q+3] = fmaxf(fmaxf(v0.w, v1.w), fmaxf(v2.w, v3.w));
    }
    uint32_t w2[16];
#pragma unroll
    for (int k = 0; k < 8; k++) {
        uint32_t hi, lo;
        split2(v[2*k], v[2*k+1], hi, lo);
        w2[pperm(k)] = hi;
        w2[8 + pperm(k)] = lo;
    }
    uint4* dst = (uint4*)&d_phB[(size_t)idx*16];
    dst[0] = make_uint4(w2[0],w2[1],w2[2],w2[3]);
    dst[1] = make_uint4(w2[4],w2[5],w2[6],w2[7]);
    dst[2] = make_uint4(w2[8],w2[9],w2[10],w2[11]);
    dst[3] = make_uint4(w2[12],w2[13],w2[14],w2[15]);
}

// ---------------- K3: denominators via warp MMA (S' = phi . theta^T) ----------
__global__ void __launch_bounds__(128)
denom_mma_kernel() {
    __shared__ __align__(16) uint32_t sth[2][128*STH_STRIDE];
    int tid = threadIdx.x, wid = tid >> 5, lane = tid & 31;
    int gid = lane >> 2, tig = lane & 3;
    int b = blockIdx.z, mt = blockIdx.x, chunk = blockIdx.y;

    int m0 = mt*128 + wid*32;
    uint32_t pa_h[2][4], pa_l[2][4];
#pragma unroll
    for (int sub = 0; sub < 2; sub++) {
        const uint32_t* ph = d_phB + (size_t)(b*MM + m0 + sub*16)*16;
        uint2 h0 = *(const uint2*)&ph[gid*16     + 2*tig];
        uint2 h1 = *(const uint2*)&ph[(gid+8)*16 + 2*tig];
        uint2 l0 = *(const uint2*)&ph[gid*16     + 8 + 2*tig];
        uint2 l1 = *(const uint2*)&ph[(gid+8)*16 + 8 + 2*tig];
        pa_h[sub][0] = h0.x; pa_h[sub][1] = h1.x; pa_h[sub][2] = h0.y; pa_h[sub][3] = h1.y;
        pa_l[sub][0] = l0.x; pa_l[sub][1] = l1.x; pa_l[sub][2] = l0.y; pa_l[sub][3] = l1.y;
    }

    int nbase = chunk*(NS/NCHUNK);
    auto load_tile = [&](int st, int buf){
        const uint4* src = (const uint4*)(d_thB + (size_t)(b*NS + nbase + st*128 + tid)*16);
        uint32_t dst = (uint32_t)__cvta_generic_to_shared(&sth[buf][tid*STH_STRIDE]);
#pragma unroll
        for (int q = 0; q < 4; q++) cp16(dst + q*16, src + q);
    };

    float acc[2][2] = {{0.f,0.f},{0.f,0.f}};
    load_tile(0, 0); cp_commit();
    const int NT = (NS/NCHUNK)/128;   // 4
    for (int st = 0; st < NT; st++) {
        int cur = st & 1;
        if (st + 1 < NT) { load_tile(st+1, cur^1); cp_commit(); cp_wait1(); }
        else cp_wait0();
        __syncthreads();
#pragma unroll 4
        for (int s8 = 0; s8 < 16; s8++) {
            int r = (s8*8 + gid)*STH_STRIDE;
            uint2 bh = *(const uint2*)&sth[cur][r + 2*tig];
            uint2 bl = *(const uint2*)&sth[cur][r + 8 + 2*tig];
            float d0[4] = {0.f,0.f,0.f,0.f};
            float d1[4] = {0.f,0.f,0.f,0.f};
            mma_bf16(d0, pa_h[0], bh.x, bh.y);
            mma_bf16(d1, pa_h[1], bh.x, bh.y);
            mma_bf16(d0, pa_h[0], bl.x, bl.y);
            mma_bf16(d1, pa_h[1], bl.x, bl.y);
            mma_bf16(d0, pa_l[0], bh.x, bh.y);
            mma_bf16(d1, pa_l[1], bh.x, bh.y);
            acc[0][0] += ex2f(d0[0]) + ex2f(d0[1]);
            acc[0][1] += ex2f(d0[2]) + ex2f(d0[3]);
            acc[1][0] += ex2f(d1[0]) + ex2f(d1[1]);
            acc[1][1] += ex2f(d1[2]) + ex2f(d1[3]);
        }
        __syncthreads();
    }
#pragma unroll
    for (int sub = 0; sub < 2; sub++) {
        float a0 = acc[sub][0], a1 = acc[sub][1];
        a0 += __shfl_xor_sync(~0u, a0, 1); a0 += __shfl_xor_sync(~0u, a0, 2);
        a1 += __shfl_xor_sync(~0u, a1, 1); a1 += __shfl_xor_sync(~0u, a1, 2);
        if (tig == 0) {
            d_denomp[(size_t)(b*MM + m0 + sub*16 + gid)*NCHUNK + chunk]     = a0;
            d_denomp[(size_t)(b*MM + m0 + sub*16 + gid + 8)*NCHUNK + chunk] = a1;
        }
    }
}

// ---------------- K4: reciprocal denominators ----------------
__global__ void rdenom_kernel() {
    int i = blockIdx.x * 256 + threadIdx.x;
    if (i >= BS*MM) return;
    const float* p = &d_denomp[(size_t)i*NCHUNK];
    float s = 0.f;
#pragma unroll
    for (int j = 0; j < NCHUNK; j++) s += p[j];
    d_rdenom[i] = 1.0f / s;
}

// ---------------- K5: pool g, fold rdenom, bf16 hi, pair-interleaved ---------
__global__ void pool64_kernel() {
    int idx = blockIdx.x * 256 + threadIdx.x;    // BS*MM*C2
    if (idx >= BS*MM*C2) return;
    int mloc = idx & 63;
    int c    = (idx >> 6) & 63;
    int mt   = (idx >> 12) & 63;
    int b    = idx >> 18;
    int m = mt*64 + mloc;
    int n = m >> 8, wp = (m >> 4) & 15, hp = m & 15;
    int sbase = n*1024 + wp*64 + hp*2;
    const float* g = d_gfull + ((size_t)b*NS)*C2 + c;
    float v = fmaxf(fmaxf(g[(size_t)(sbase)*C2],    g[(size_t)(sbase+1)*C2]),
                    fmaxf(g[(size_t)(sbase+32)*C2], g[(size_t)(sbase+33)*C2]));
    v *= d_rdenom[b*MM + m];
    int chunk = mloc >> 4, m16 = mloc & 15, w = m16 >> 1, ln = m16 & 1;
    int newmloc = chunk*16 + pperm(w)*2 + ln;
    size_t ei = (size_t)((b*64 + mt)*64 + c)*64 + newmloc;
    ((__nv_bfloat16*)d_gthi)[ei] = __float2bfloat16_rn(v);
}

// ---------------- K6: attention via warp MMA (R10 champion config) -----------
__global__ void __launch_bounds__(256, 2)
attn_mma_kernel() {
    __shared__ __align__(16) uint32_t sphi[2][64*SPH_STRIDE];  // 2 x 6 KB
    __shared__ __align__(16) uint32_t sgh[2][64*SGH_STRIDE];   // 2 x 10 KB
    int tid = threadIdx.x, wid = tid >> 5, lane = tid & 31;
    int gid = lane >> 2, tig = lane & 3;
    int b = blockIdx.y, nt = blockIdx.x, z = blockIdx.z;
    int n0 = nt*128 + wid*16;

    const uint32_t* th = d_thB + (size_t)(b*NS + n0)*16;
    uint32_t tah[4], tal[4];
    {
        uint2 h0 = *(const uint2*)&th[gid*16     + 2*tig];
        uint2 h1 = *(const uint2*)&th[(gid+8)*16 + 2*tig];
        uint2 l0 = *(const uint2*)&th[gid*16     + 8 + 2*tig];
        uint2 l1 = *(const uint2*)&th[(gid+8)*16 + 8 + 2*tig];
        tah[0] = h0.x; tah[1] = h1.x; tah[2] = h0.y; tah[3] = h1.y;
        tal[0] = l0.x; tal[1] = l1.x; tal[2] = l0.y; tal[3] = l1.y;
    }

    auto load_tile = [&](int mt, int buf){
        int row = tid >> 2, q = tid & 3;
        uint32_t pd = (uint32_t)__cvta_generic_to_shared(&sphi[buf][row*SPH_STRIDE + q*4]);
        cp16(pd, d_phB + (size_t)(b*MM + mt*64 + row)*16 + q*4);
        const uint32_t* gsrc = d_gthi + (size_t)((b*64 + mt)*64 + row)*32 + q*8;
        uint32_t gd = (uint32_t)__cvta_generic_to_shared(&sgh[buf][row*SGH_STRIDE + q*8]);
        cp16(gd,      gsrc);
        cp16(gd + 16, gsrc + 4);
    };

    float acc[8][4];
#pragma unroll
    for (int ct = 0; ct < 8; ct++)
#pragma unroll
        for (int j = 0; j < 4; j++) acc[ct][j] = 0.f;

    int mt0 = z*32;
    load_tile(mt0, 0); cp_commit();
    for (int t = 0; t < 32; t++) {
        int cur = t & 1;
        if (t + 1 < 32) { load_tile(mt0 + t + 1, cur^1); cp_commit(); cp_wait1(); }
        else cp_wait0();
        __syncthreads();

#pragma unroll
        for (int k = 0; k < 4; k++) {
            uint32_t aeh[4];
            float s0[4] = {0.f,0.f,0.f,0.f};
            float s1[4] = {0.f,0.f,0.f,0.f};
            {
                int r = ((2*k)*8 + gid)*SPH_STRIDE;
                uint2 bh = *(const uint2*)&sphi[cur][r + 2*tig];
                uint2 bl = *(const uint2*)&sphi[cur][r + 8 + 2*tig];
                mma_bf16(s0, tah, bh.x, bh.y);
                mma_bf16(s0, tal, bh.x, bh.y);
                mma_bf16(s0, tah, bl.x, bl.y);
            }
            {
                int r = ((2*k+1)*8 + gid)*SPH_STRIDE;
                uint2 bh = *(const uint2*)&sphi[cur][r + 2*tig];
                uint2 bl = *(const uint2*)&sphi[cur][r + 8 + 2*tig];
                mma_bf16(s1, tah, bh.x, bh.y);
                mma_bf16(s1, tal, bh.x, bh.y);
                mma_bf16(s1, tah, bl.x, bl.y);
            }
            aeh[0] = cvt_bf16x2(ex2f(s0[0]), ex2f(s0[1]));
            aeh[1] = cvt_bf16x2(ex2f(s0[2]), ex2f(s0[3]));
            aeh[2] = cvt_bf16x2(ex2f(s1[0]), ex2f(s1[1]));
            aeh[3] = cvt_bf16x2(ex2f(s1[2]), ex2f(s1[3]));
#pragma unroll
            for (int ct = 0; ct < 8; ct++) {
                int cbase = (ct*8 + gid)*SGH_STRIDE + 8*k;
                uint2 bg = *(const uint2*)&sgh[cur][cbase + 2*tig];
                mma_bf16(acc[ct], aeh, bg.x, bg.y);
            }
        }
        __syncthreads();
    }

    float* outb = d_attng + (size_t)z*BS*NS*C2;
    int n = n0 + gid;
#pragma unroll
    for (int ct = 0; ct < 8; ct++) {
        int c = ct*8 + tig*2;
        *(float2*)&outb[(size_t)(b*NS + n)*C2 + c]     = make_float2(acc[ct][0], acc[ct][1]);
        *(float2*)&outb[(size_t)(b*NS + n + 8)*C2 + c] = make_float2(acc[ct][2], acc[ct][3]);
    }
}

// ---------------- K7: final conv + blend (256 thr: halves split o-range) -----
__global__ void __launch_bounds__(256)
out_kernel(const float* __restrict__ x,
           const float* __restrict__ wag, const float* __restrict__ bag,
           const float* __restrict__ gamma, float* __restrict__ out) {
    __shared__ float sw[CH*C2];   // [o][c]
    __shared__ float sb[CH];
    int tid = threadIdx.x;
    for (int i = tid; i < CH*C2; i += 256) sw[i] = wag[i];
    if (tid < CH) sb[tid] = bag[tid];
    __syncthreads();

    float alpha = 1.0f / (1.0f + expf(-gamma[0]));
    int half = tid >> 7;           // o in [half*64, half*64+64)
    int lt   = tid & 127;
    int ob   = half * 64;
    int b = blockIdx.y;
    int s = blockIdx.x * 128 + lt;

    float4 a[16];
    {
        const float4* ap0 = (const float4*)&d_attng[((size_t)b*NS + s)*C2];
        const float4* ap1 = (const float4*)&d_attng[(size_t)BS*NS*C2 + ((size_t)b*NS + s)*C2];
#pragma unroll
        for (int j = 0; j < 16; j++) {
            float4 u = ap0[j], v = ap1[j];
            a[j] = make_float4(u.x + v.x, u.y + v.y, u.z + v.z, u.w + v.w);
        }
    }

    const float* xp = x + (size_t)b*CH*NS + s;
    float* o0p = out + (size_t)b*CH*NS + s;
    float* o1p = o0p + (size_t)BS*CH*NS;

#pragma unroll 2
    for (int oi = 0; oi < 64; oi++) {
        int o = ob + oi;
        const float4* wr = (const float4*)(sw + o*C2);
        float y0 = sb[o], y1 = 0.f, y2 = 0.f, y3 = 0.f;
#pragma unroll
        for (int j = 0; j < 16; j += 4) {
            float4 w;
            w = wr[j+0]; y0 = fmaf(a[j+0].x, w.x, y0); y0 = fmaf(a[j+0].y, w.y, y0);
                         y0 = fmaf(a[j+0].z, w.z, y0); y0 = fmaf(a[j+0].w, w.w, y0);
            w = wr[j+1]; y1 = fmaf(a[j+1].x, w.x, y1); y1 = fmaf(a[j+1].y, w.y, y1);
                         y1 = fmaf(a[j+1].z, w.z, y1); y1 = fmaf(a[j+1].w, w.w, y1);
            w = wr[j+2]; y2 = fmaf(a[j+2].x, w.x, y2); y2 = fmaf(a[j+2].y, w.y, y2);
                         y2 = fmaf(a[j+2].z, w.z, y2); y2 = fmaf(a[j+2].w, w.w, y2);
            w = wr[j+3]; y3 = fmaf(a[j+3].x, w.x, y3); y3 = fmaf(a[j+3].y, w.y, y3);
                         y3 = fmaf(a[j+3].z, w.z, y3); y3 = fmaf(a[j+3].w, w.w, y3);
        }
        float y = (y0 + y1) + (y2 + y3);
        float xv = xp[(size_t)o*NS];
        o0p[(size_t)o*NS] = (1.0f - alpha)*xv + alpha*y;
        o1p[(size_t)o*NS] = y;
    }
}

// ---------------- launch ----------------
extern "C" void kernel_launch(void* const* d_in, const int* in_sizes, int n_in,
                              void* d_out, int out_size) {
    const float* x     = (const float*)d_in[0];
    const float* wth   = (const float*)d_in[1];
    const float* bth   = (const float*)d_in[2];
    const float* wph   = (const float*)d_in[3];
    const float* bph   = (const float*)d_in[4];
    const float* wg    = (const float*)d_in[5];
    const float* bg    = (const float*)d_in[6];
    const float* wag   = (const float*)d_in[7];
    const float* bag   = (const float*)d_in[8];
    const float* gamma = (const float*)d_in[9];
    float* out = (float*)d_out;

    proj16_kernel<<<dim3(NS/128, BS), 256>>>(x, wth, bth, wph, bph);
    proj64_kernel<<<dim3(NS/128, BS), 256>>>(x, wg, bg);
    pool16_kernel<<<(BS*MM + 127)/128, 128>>>();
    denom_mma_kernel<<<dim3(MM/128, NCHUNK, BS), 128>>>();
    rdenom_kernel<<<(BS*MM + 255)/256, 256>>>();
    pool64_kernel<<<(BS*MM*C2 + 255)/256, 256>>>();
    attn_mma_kernel<<<dim3(NS/128, BS, 2), 256>>>();
    out_kernel<<<dim3(NS/128, BS), 256>>>(x, wag, bag, gamma, out);
}